// round 8
// baseline (speedup 1.0000x reference)
#include <cuda_runtime.h>
#include <math.h>
#include <stdint.h>

#define B_    256
#define NIN_  6912
#define SLOTS 8

#define NPB   64            // n per block
#define NCH   4             // n per stage
#define NSTG  (NPB / NCH)   // 16 stages
#define NBUF  3

typedef unsigned long long ull;

#define FFMA2(d, a, b, c) \
    asm("fma.rn.f32x2 %0, %1, %2, %3;" : "=l"(d) : "l"(a), "l"(b), "l"(c))
#define FMUL2(d, a, b) \
    asm("mul.rn.f32x2 %0, %1, %2;" : "=l"(d) : "l"(a), "l"(b))
#define PACK2(d, lo, hi) \
    asm("mov.b64 %0, {%1, %2};" : "=l"(d) : "f"(lo), "f"(hi))
#define UNPACK2(lo, hi, v) \
    asm("mov.b64 {%0, %1}, %2;" : "=f"(lo), "=f"(hi) : "l"(v))

__device__ __forceinline__ uint32_t s2u(const void* p) {
    return (uint32_t)__cvta_generic_to_shared(p);
}
__device__ __forceinline__ void cp16(const void* sdst, const void* gsrc) {
    asm volatile("cp.async.cg.shared.global [%0], [%1], 16;"
                 :: "r"(s2u(sdst)), "l"(gsrc) : "memory");
}
#define CP_COMMIT() asm volatile("cp.async.commit_group;" ::: "memory")
template <int N>
__device__ __forceinline__ void cp_wait() {
    asm volatile("cp.async.wait_group %0;" :: "n"(N) : "memory");
}

// Scratch: s1/s2 transposed [slot][k][b] (k=j*16+e); v1 [b][k].
__device__ float g_s1[SLOTS * B_ * 32];
__device__ float g_s2[SLOTS * B_ * 32];
__device__ __align__(16) float g_v1[B_ * 32];

__global__ void zero_kernel() {
    int i = blockIdx.x * blockDim.x + threadIdx.x;
    if (i < SLOTS * B_ * 32) { g_s1[i] = 0.0f; g_s2[i] = 0.0f; }
}

__device__ __forceinline__ void squash16(const float* s, float* v) {
    float n2 = 0.0f;
#pragma unroll
    for (int e = 0; e < 16; ++e) n2 = fmaf(s[e], s[e], n2);
    float f = n2 / ((1.0f + n2) * sqrtf(n2 + 1e-9f));
#pragma unroll
    for (int e = 0; e < 16; ++e) v[e] = s[e] * f;
}

// ======================= Pass 1 =======================
// Lane = (j, eq, bq): j = lane&1, eq = (lane>>1)&3, bq = lane>>3.
// Thread owns e in {eq, 4+eq, 8+eq, 12+eq} (interleaved) and 2 b's.
// Warp covers 8 b, block (8 warps) covers 64 b. grid = (108, 4).
__global__ __launch_bounds__(256, 3) void pass1_kernel(const ulonglong2* __restrict__ X,
                                                       const float4* __restrict__ Wg) {
    __shared__ float4 Wd[NBUF][NCH][2][33];       // [buf][nl][j][e*2+h] (+pad)
    __shared__ float4 xs[NBUF][64][NCH * 2 + 1];  // [buf][bl][nl*2+h] (+pad)

    const int tid  = threadIdx.x;
    const int w    = tid >> 5;
    const int lane = tid & 31;
    const int j    = lane & 1;
    const int eq   = (lane >> 1) & 3;
    const int bq   = lane >> 3;
    const int lb0  = w * 8 + bq * 2, lb1 = lb0 + 1;
    const int bB   = blockIdx.y * 64;
    const int nbase = blockIdx.x * NPB;

    ull acc0[4], acc1[4];
    ull zero; PACK2(zero, 0.0f, 0.0f);
#pragma unroll
    for (int ei = 0; ei < 4; ++ei) { acc0[ei] = zero; acc1[ei] = zero; }

    auto issue = [&](int s) {
        const int buf = s % NBUF;
        const int n0  = nbase + s * NCH;
        {   // W: 256 float4 per stage, 1 per thread
            int f  = tid;
            int jj = f >> 7, nl = (f >> 5) & 3, q = f & 31;
            cp16(&Wd[buf][nl][jj][q],
                 Wg + ((size_t)(jj * NIN_ + n0 + nl)) * 32 + q);
        }
#pragma unroll
        for (int it = 0; it < 2; ++it) {   // x: 512 float4, 2 per thread
            int f  = it * 256 + tid;
            int bl = f >> 3, q = f & 7, nl = q >> 1, h = q & 1;
            cp16(&xs[buf][bl][q],
                 (const float4*)X + ((size_t)(bB + bl) * NIN_ + n0 + nl) * 2 + h);
        }
        CP_COMMIT();
    };

    auto compute = [&](int s) {
        const int buf = s % NBUF;
#pragma unroll
        for (int nl = 0; nl < NCH; ++nl) {
            const ulonglong2 xa0 = *reinterpret_cast<const ulonglong2*>(&xs[buf][lb0][nl * 2]);
            const ulonglong2 xa1 = *reinterpret_cast<const ulonglong2*>(&xs[buf][lb0][nl * 2 + 1]);
            const ulonglong2 xb0 = *reinterpret_cast<const ulonglong2*>(&xs[buf][lb1][nl * 2]);
            const ulonglong2 xb1 = *reinterpret_cast<const ulonglong2*>(&xs[buf][lb1][nl * 2 + 1]);
#pragma unroll
            for (int ei = 0; ei < 4; ++ei) {
                const int q = (ei * 4 + eq) * 2;   // e = ei*4 + eq
                const ulonglong2 wA = *reinterpret_cast<const ulonglong2*>(&Wd[buf][nl][j][q]);
                const ulonglong2 wB = *reinterpret_cast<const ulonglong2*>(&Wd[buf][nl][j][q + 1]);
                ull a = acc0[ei];
                FFMA2(a, wA.x, xa0.x, a); FFMA2(a, wA.y, xa0.y, a);
                FFMA2(a, wB.x, xa1.x, a); FFMA2(a, wB.y, xa1.y, a);
                acc0[ei] = a;
                ull b = acc1[ei];
                FFMA2(b, wA.x, xb0.x, b); FFMA2(b, wA.y, xb0.y, b);
                FFMA2(b, wB.x, xb1.x, b); FFMA2(b, wB.y, xb1.y, b);
                acc1[ei] = b;
            }
        }
    };

    issue(0);
    issue(1);
#pragma unroll 3
    for (int s = 0; s < NSTG; ++s) {
        cp_wait<1>();
        __syncthreads();
        compute(s);
        if (s + 2 < NSTG) issue(s + 2); else CP_COMMIT();
    }

    float* dst = g_s1 + (blockIdx.x & (SLOTS - 1)) * (B_ * 32);
#pragma unroll
    for (int ei = 0; ei < 4; ++ei) {
        const int k = j * 16 + ei * 4 + eq;
        float lo, hi;
        UNPACK2(lo, hi, acc0[ei]);
        atomicAdd(dst + k * B_ + bB + lb0, lo + hi);
        UNPACK2(lo, hi, acc1[ei]);
        atomicAdd(dst + k * B_ + bB + lb1, lo + hi);
    }
}

// ======================= v1 = squash(0.5 * sum_slots s1) =======================
__global__ void v1_kernel() {
    __shared__ float s[32][B_];
    const int tid = threadIdx.x;
    const int b   = tid & 255;
    const int kg  = tid >> 8;
#pragma unroll
    for (int i = 0; i < 8; ++i) {
        int k = kg * 8 + i;
        float a = 0.0f;
#pragma unroll
        for (int sl = 0; sl < SLOTS; ++sl)
            a += g_s1[sl * (B_ * 32) + k * B_ + b];
        s[k][b] = a * 0.5f;
    }
    __syncthreads();
    if (tid < 512) {
        int bb = tid >> 1, j = tid & 1;
        float sv[16], v[16];
#pragma unroll
        for (int e = 0; e < 16; ++e) sv[e] = s[j * 16 + e][bb];
        squash16(sv, v);
#pragma unroll
        for (int e = 0; e < 16; ++e) g_v1[bb * 32 + j * 16 + e] = v[e];
    }
}

// ======================= Pass 2 =======================
// Lane = (j, eq, bq): thread owns 1 b, 4 interleaved e. Warp covers 4 b,
// block covers 32 b. Logit reduced over eq lanes via shfl. grid = (108, 8).
__global__ __launch_bounds__(256, 3) void pass2_kernel(const ulonglong2* __restrict__ X,
                                                       const float4* __restrict__ Wg) {
    __shared__ float4 Wd[NBUF][NCH][2][33];
    __shared__ float4 xs[NBUF][32][NCH * 2 + 1];

    const int tid  = threadIdx.x;
    const int w    = tid >> 5;
    const int lane = tid & 31;
    const int j    = lane & 1;
    const int eq   = (lane >> 1) & 3;
    const int bq   = lane >> 3;
    const int lb   = w * 4 + bq;
    const int bB   = blockIdx.y * 32;
    const int b    = bB + lb;
    const int nbase = blockIdx.x * NPB;

    // v1 for (b, j, my 4 e's), duplicated into both f32x2 halves
    ull v1d[4];
#pragma unroll
    for (int ei = 0; ei < 4; ++ei) {
        float v = g_v1[b * 32 + j * 16 + ei * 4 + eq];
        PACK2(v1d[ei], v, v);
    }

    ull acc2[4];
    ull zero; PACK2(zero, 0.0f, 0.0f);
#pragma unroll
    for (int ei = 0; ei < 4; ++ei) acc2[ei] = zero;

    auto issue = [&](int s) {
        const int buf = s % NBUF;
        const int n0  = nbase + s * NCH;
        {   // W: 256 float4 per stage, 1 per thread
            int f  = tid;
            int jj = f >> 7, nl = (f >> 5) & 3, q = f & 31;
            cp16(&Wd[buf][nl][jj][q],
                 Wg + ((size_t)(jj * NIN_ + n0 + nl)) * 32 + q);
        }
        {   // x: 256 float4, 1 per thread
            int f  = tid;
            int bl = f >> 3, q = f & 7, nl = q >> 1, h = q & 1;
            cp16(&xs[buf][bl][q],
                 (const float4*)X + ((size_t)(bB + bl) * NIN_ + n0 + nl) * 2 + h);
        }
        CP_COMMIT();
    };

    auto compute = [&](int s) {
        const int buf = s % NBUF;
#pragma unroll
        for (int nl = 0; nl < NCH; ++nl) {
            const ulonglong2 x0 = *reinterpret_cast<const ulonglong2*>(&xs[buf][lb][nl * 2]);
            const ulonglong2 x1 = *reinterpret_cast<const ulonglong2*>(&xs[buf][lb][nl * 2 + 1]);

            ull u2[4];
            ull t2 = zero;
#pragma unroll
            for (int ei = 0; ei < 4; ++ei) {
                const int q = (ei * 4 + eq) * 2;
                const ulonglong2 wA = *reinterpret_cast<const ulonglong2*>(&Wd[buf][nl][j][q]);
                const ulonglong2 wB = *reinterpret_cast<const ulonglong2*>(&Wd[buf][nl][j][q + 1]);
                ull t;
                FMUL2(t, wA.x, x0.x);
                FFMA2(t, wA.y, x0.y, t);
                FFMA2(t, wB.x, x1.x, t);
                FFMA2(t, wB.y, x1.y, t);
                u2[ei] = t;
                FFMA2(t2, v1d[ei], t, t2);
            }
            float tlo, thi;
            UNPACK2(tlo, thi, t2);
            float t = tlo + thi;
            // reduce over the 4 eq lanes (same b, same j)
            t += __shfl_xor_sync(0xffffffffu, t, 2);
            t += __shfl_xor_sync(0xffffffffu, t, 4);
            float to = __shfl_xor_sync(0xffffffffu, t, 1);   // partner capsule
            float c  = __fdividef(1.0f, 1.0f + __expf(to - t));
            ull cd; PACK2(cd, c, c);
#pragma unroll
            for (int ei = 0; ei < 4; ++ei)
                FFMA2(acc2[ei], cd, u2[ei], acc2[ei]);
        }
    };

    issue(0);
    issue(1);
#pragma unroll 3
    for (int s = 0; s < NSTG; ++s) {
        cp_wait<1>();
        __syncthreads();
        compute(s);
        if (s + 2 < NSTG) issue(s + 2); else CP_COMMIT();
    }

    float* dst = g_s2 + (blockIdx.x & (SLOTS - 1)) * (B_ * 32);
#pragma unroll
    for (int ei = 0; ei < 4; ++ei) {
        const int k = j * 16 + ei * 4 + eq;
        float lo, hi;
        UNPACK2(lo, hi, acc2[ei]);
        atomicAdd(dst + k * B_ + b, lo + hi);
    }
}

// ======================= Output: v = squash(sum_slots s2) =======================
__global__ void squash_out_kernel(float* __restrict__ out) {
    __shared__ float s[32][B_];
    const int tid = threadIdx.x;
    const int b   = tid & 255;
    const int kg  = tid >> 8;
#pragma unroll
    for (int i = 0; i < 8; ++i) {
        int k = kg * 8 + i;
        float a = 0.0f;
#pragma unroll
        for (int sl = 0; sl < SLOTS; ++sl)
            a += g_s2[sl * (B_ * 32) + k * B_ + b];
        s[k][b] = a;
    }
    __syncthreads();
    if (tid < 512) {
        int bb = tid >> 1, j = tid & 1;
        float sv[16], v[16];
#pragma unroll
        for (int e = 0; e < 16; ++e) sv[e] = s[j * 16 + e][bb];
        squash16(sv, v);
#pragma unroll
        for (int e = 0; e < 16; ++e) out[bb * 32 + j * 16 + e] = v[e];
    }
}

extern "C" void kernel_launch(void* const* d_in, const int* in_sizes, int n_in,
                              void* d_out, int out_size) {
    const ulonglong2* X = (const ulonglong2*)d_in[0];   // x: [256, 6912, 8] f32
    const float4* W = (const float4*)d_in[1];           // W: [2, 6912, 16, 8] f32
    float* out = (float*)d_out;                         // v: [256, 2, 16] f32

    zero_kernel<<<(SLOTS * B_ * 32 + 255) / 256, 256>>>();

    dim3 g1(NIN_ / NPB, B_ / 64);    // 108 x 4
    pass1_kernel<<<g1, 256>>>(X, W);

    v1_kernel<<<1, 1024>>>();

    dim3 g2(NIN_ / NPB, B_ / 32);    // 108 x 8
    pass2_kernel<<<g2, 256>>>(X, W);

    squash_out_kernel<<<1, 1024>>>(out);
}

// round 9
// speedup vs baseline: 1.3938x; 1.3938x over previous
#include <cuda_runtime.h>
#include <math.h>
#include <stdint.h>

#define B_    256
#define NIN_  6912
#define SLOTS 8

#define NPB   24            // n per block
#define NST   2             // n per stage
#define NSTG  (NPB / NST)   // 12 stages
#define NBUF  4
#define DEPTH 3             // groups in flight

typedef unsigned long long ull;

#define FFMA2(d, a, b, c) \
    asm("fma.rn.f32x2 %0, %1, %2, %3;" : "=l"(d) : "l"(a), "l"(b), "l"(c))
#define FMUL2(d, a, b) \
    asm("mul.rn.f32x2 %0, %1, %2;" : "=l"(d) : "l"(a), "l"(b))
#define PACK2(d, lo, hi) \
    asm("mov.b64 %0, {%1, %2};" : "=l"(d) : "f"(lo), "f"(hi))
#define UNPACK2(lo, hi, v) \
    asm("mov.b64 {%0, %1}, %2;" : "=f"(lo), "=f"(hi) : "l"(v))

__device__ __forceinline__ uint32_t s2u(const void* p) {
    return (uint32_t)__cvta_generic_to_shared(p);
}
__device__ __forceinline__ void cp16(const void* sdst, const void* gsrc) {
    asm volatile("cp.async.cg.shared.global [%0], [%1], 16;"
                 :: "r"(s2u(sdst)), "l"(gsrc) : "memory");
}
#define CP_COMMIT() asm volatile("cp.async.commit_group;" ::: "memory")
template <int N>
__device__ __forceinline__ void cp_wait() {
    asm volatile("cp.async.wait_group %0;" :: "n"(N) : "memory");
}

// Scratch: s1/s2 transposed [slot][k][b] (k=j*16+e); v1 [b][k].
__device__ float g_s1[SLOTS * B_ * 32];
__device__ float g_s2[SLOTS * B_ * 32];
__device__ __align__(16) float g_v1[B_ * 32];

__global__ void zero_kernel() {
    int i = blockIdx.x * blockDim.x + threadIdx.x;
    if (i < SLOTS * B_ * 32) { g_s1[i] = 0.0f; g_s2[i] = 0.0f; }
}

__device__ __forceinline__ void squash16(const float* s, float* v) {
    float n2 = 0.0f;
#pragma unroll
    for (int e = 0; e < 16; ++e) n2 = fmaf(s[e], s[e], n2);
    float f = n2 / ((1.0f + n2) * sqrtf(n2 + 1e-9f));
#pragma unroll
    for (int e = 0; e < 16; ++e) v[e] = s[e] * f;
}

// ======================= Pass 1 =======================
// 128 threads: j = tid&1, bp = tid>>1 -> b = {2bp, 2bp+1}. 24 n per block,
// 12 stages x 2 n, 4-buffer depth-3 cp.async pipeline.
#define P1_THR 128

__global__ __launch_bounds__(P1_THR, 4) void pass1_kernel(const float4* __restrict__ X,
                                                          const float4* __restrict__ Wg) {
    __shared__ float4 Wd[NBUF][NST][16][2][2];        // [buf][nl][e][h][j]
    __shared__ float4 xs[NBUF][128][NST * 2 + 1];     // [buf][bl][nl*2+h]

    const int tid   = threadIdx.x;
    const int j     = tid & 1;
    const int bp    = tid >> 1;
    const int lb0   = bp * 2, lb1 = bp * 2 + 1;
    const int gbb   = blockIdx.y * 128;
    const int nbase = blockIdx.x * NPB;

    ull acc0[16], acc1[16];
    ull zero; PACK2(zero, 0.0f, 0.0f);
#pragma unroll
    for (int e = 0; e < 16; ++e) { acc0[e] = zero; acc1[e] = zero; }

    auto issue = [&](int s) {
        const int buf = s & (NBUF - 1);
        const int n0  = nbase + s * NST;
        {   // W: 128 float4 per stage, 1 per thread
            int f  = tid;
            int jj = f & 1, h = (f >> 1) & 1, e = (f >> 2) & 15, nl = (f >> 6) & 1;
            cp16(&Wd[buf][nl][e][h][jj],
                 Wg + ((size_t)(jj * NIN_ + n0 + nl) * 16 + e) * 2 + h);
        }
#pragma unroll
        for (int it = 0; it < 4; ++it) {   // x: 512 float4, 4 per thread
            int f = it * P1_THR + tid;
            int bl = f >> 2, q = f & 3, nl = q >> 1, h = q & 1;
            cp16(&xs[buf][bl][q],
                 X + ((size_t)(gbb + bl) * NIN_ + n0 + nl) * 2 + h);
        }
        CP_COMMIT();
    };

    auto compute = [&](int s) {
        const int buf = s & (NBUF - 1);
#pragma unroll
        for (int nl = 0; nl < NST; ++nl) {
            const ulonglong2 xa0 = *reinterpret_cast<const ulonglong2*>(&xs[buf][lb0][nl * 2]);
            const ulonglong2 xa1 = *reinterpret_cast<const ulonglong2*>(&xs[buf][lb0][nl * 2 + 1]);
            const ulonglong2 xb0 = *reinterpret_cast<const ulonglong2*>(&xs[buf][lb1][nl * 2]);
            const ulonglong2 xb1 = *reinterpret_cast<const ulonglong2*>(&xs[buf][lb1][nl * 2 + 1]);
#pragma unroll
            for (int e = 0; e < 16; ++e) {
                const ulonglong2 wA = *reinterpret_cast<const ulonglong2*>(&Wd[buf][nl][e][0][j]);
                const ulonglong2 wB = *reinterpret_cast<const ulonglong2*>(&Wd[buf][nl][e][1][j]);
                ull a = acc0[e];
                FFMA2(a, wA.x, xa0.x, a); FFMA2(a, wA.y, xa0.y, a);
                FFMA2(a, wB.x, xa1.x, a); FFMA2(a, wB.y, xa1.y, a);
                acc0[e] = a;
                ull b = acc1[e];
                FFMA2(b, wA.x, xb0.x, b); FFMA2(b, wA.y, xb0.y, b);
                FFMA2(b, wB.x, xb1.x, b); FFMA2(b, wB.y, xb1.y, b);
                acc1[e] = b;
            }
        }
    };

    issue(0); issue(1); issue(2);
#pragma unroll 4
    for (int s = 0; s < NSTG; ++s) {
        cp_wait<DEPTH - 1>();
        __syncthreads();                       // compute(s-1) done block-wide
        if (s + DEPTH < NSTG) issue(s + DEPTH); else CP_COMMIT();
        compute(s);
    }

    float* dst = g_s1 + (blockIdx.x & (SLOTS - 1)) * (B_ * 32);
#pragma unroll
    for (int e = 0; e < 16; ++e) {
        float lo, hi;
        UNPACK2(lo, hi, acc0[e]);
        atomicAdd(dst + (j * 16 + e) * B_ + gbb + lb0, lo + hi);
        UNPACK2(lo, hi, acc1[e]);
        atomicAdd(dst + (j * 16 + e) * B_ + gbb + lb1, lo + hi);
    }
}

// ======================= v1 = squash(0.5 * sum_slots s1) =======================
__global__ void v1_kernel() {
    __shared__ float s[32][B_];
    const int tid = threadIdx.x;
    const int b   = tid & 255;
    const int kg  = tid >> 8;
#pragma unroll
    for (int i = 0; i < 8; ++i) {
        int k = kg * 8 + i;
        float a = 0.0f;
#pragma unroll
        for (int sl = 0; sl < SLOTS; ++sl)
            a += g_s1[sl * (B_ * 32) + k * B_ + b];
        s[k][b] = a * 0.5f;
    }
    __syncthreads();
    if (tid < 512) {
        int bb = tid >> 1, j = tid & 1;
        float sv[16], v[16];
#pragma unroll
        for (int e = 0; e < 16; ++e) sv[e] = s[j * 16 + e][bb];
        squash16(sv, v);
#pragma unroll
        for (int e = 0; e < 16; ++e) g_v1[bb * 32 + j * 16 + e] = v[e];
    }
}

// ======================= Pass 2 =======================
// 256 threads: j = tid&1, bl = tid>>1 (128 b). 24 n per block, 12 stages x 2 n,
// 4-buffer depth-3 pipeline, interleaved softmax chains.
#define P2_THR 256

__global__ __launch_bounds__(P2_THR, 2) void pass2_kernel(const float4* __restrict__ X,
                                                          const float4* __restrict__ Wg) {
    __shared__ float4 Wd[NBUF][NST][16][2][2];
    __shared__ float4 xs[NBUF][128][NST * 2 + 1];

    const int tid   = threadIdx.x;
    const int j     = tid & 1;
    const int bl    = tid >> 1;
    const int gbb   = blockIdx.y * 128;
    const int b     = gbb + bl;
    const int nbase = blockIdx.x * NPB;

    // v1 for (b, j), packed into e-pairs
    ull v1p[8];
    {
        const float4* vp = reinterpret_cast<const float4*>(g_v1 + b * 32 + j * 16);
#pragma unroll
        for (int q = 0; q < 4; ++q) {
            float4 v = vp[q];
            PACK2(v1p[2 * q],     v.x, v.y);
            PACK2(v1p[2 * q + 1], v.z, v.w);
        }
    }

    ull accp[8];
    ull zero; PACK2(zero, 0.0f, 0.0f);
#pragma unroll
    for (int q = 0; q < 8; ++q) accp[q] = zero;

    auto issue = [&](int s) {
        const int buf = s & (NBUF - 1);
        const int n0  = nbase + s * NST;
        if (tid < 128) {   // W: 128 float4 per stage
            int f  = tid;
            int jj = f & 1, h = (f >> 1) & 1, e = (f >> 2) & 15, nl = (f >> 6) & 1;
            cp16(&Wd[buf][nl][e][h][jj],
                 Wg + ((size_t)(jj * NIN_ + n0 + nl) * 16 + e) * 2 + h);
        }
#pragma unroll
        for (int it = 0; it < 2; ++it) {   // x: 512 float4, 2 per thread
            int f = it * P2_THR + tid;
            int b2 = f >> 2, q = f & 3, nl = q >> 1, h = q & 1;
            cp16(&xs[buf][b2][q],
                 X + ((size_t)(gbb + b2) * NIN_ + n0 + nl) * 2 + h);
        }
        CP_COMMIT();
    };

    auto compute = [&](int s) {
        const int buf = s & (NBUF - 1);
        ull up[NST][8];
        float tj[NST];

        // Phase A: u + logit partials for BOTH n (independent -> ILP)
#pragma unroll
        for (int nl = 0; nl < NST; ++nl) {
            const ulonglong2 x0 = *reinterpret_cast<const ulonglong2*>(&xs[buf][bl][nl * 2]);
            const ulonglong2 x1 = *reinterpret_cast<const ulonglong2*>(&xs[buf][bl][nl * 2 + 1]);
            ull t2 = zero;
#pragma unroll
            for (int q = 0; q < 8; ++q) {
                const int e0 = 2 * q, e1 = 2 * q + 1;
                const ulonglong2 wA0 = *reinterpret_cast<const ulonglong2*>(&Wd[buf][nl][e0][0][j]);
                const ulonglong2 wB0 = *reinterpret_cast<const ulonglong2*>(&Wd[buf][nl][e0][1][j]);
                const ulonglong2 wA1 = *reinterpret_cast<const ulonglong2*>(&Wd[buf][nl][e1][0][j]);
                const ulonglong2 wB1 = *reinterpret_cast<const ulonglong2*>(&Wd[buf][nl][e1][1][j]);
                ull ta, tb;
                FMUL2(ta, wA0.x, x0.x);
                FFMA2(ta, wA0.y, x0.y, ta);
                FFMA2(ta, wB0.x, x1.x, ta);
                FFMA2(ta, wB0.y, x1.y, ta);
                FMUL2(tb, wA1.x, x0.x);
                FFMA2(tb, wA1.y, x0.y, tb);
                FFMA2(tb, wB1.x, x1.x, tb);
                FFMA2(tb, wB1.y, x1.y, tb);
                float alo, ahi, blo, bhi;
                UNPACK2(alo, ahi, ta);
                UNPACK2(blo, bhi, tb);
                ull u;
                PACK2(u, alo + ahi, blo + bhi);
                up[nl][q] = u;
                FFMA2(t2, v1p[q], u, t2);
            }
            float tlo, thi;
            UNPACK2(tlo, thi, t2);
            tj[nl] = tlo + thi;
        }

        // Phase B: both shfl/exp/div chains back-to-back (overlap)
        float c[NST];
#pragma unroll
        for (int nl = 0; nl < NST; ++nl) {
            float to = __shfl_xor_sync(0xffffffffu, tj[nl], 1);
            c[nl] = __fdividef(1.0f, 1.0f + __expf(to - tj[nl]));
        }

        // Phase C: accumulate
#pragma unroll
        for (int nl = 0; nl < NST; ++nl) {
            ull cd; PACK2(cd, c[nl], c[nl]);
#pragma unroll
            for (int q = 0; q < 8; ++q)
                FFMA2(accp[q], cd, up[nl][q], accp[q]);
        }
    };

    issue(0); issue(1); issue(2);
#pragma unroll 4
    for (int s = 0; s < NSTG; ++s) {
        cp_wait<DEPTH - 1>();
        __syncthreads();
        if (s + DEPTH < NSTG) issue(s + DEPTH); else CP_COMMIT();
        compute(s);
    }

    float* dst = g_s2 + (blockIdx.x & (SLOTS - 1)) * (B_ * 32);
#pragma unroll
    for (int q = 0; q < 8; ++q) {
        float lo, hi;
        UNPACK2(lo, hi, accp[q]);
        atomicAdd(dst + (j * 16 + 2 * q) * B_ + b,     lo);
        atomicAdd(dst + (j * 16 + 2 * q + 1) * B_ + b, hi);
    }
}

// ======================= Output: v = squash(sum_slots s2) =======================
__global__ void squash_out_kernel(float* __restrict__ out) {
    __shared__ float s[32][B_];
    const int tid = threadIdx.x;
    const int b   = tid & 255;
    const int kg  = tid >> 8;
#pragma unroll
    for (int i = 0; i < 8; ++i) {
        int k = kg * 8 + i;
        float a = 0.0f;
#pragma unroll
        for (int sl = 0; sl < SLOTS; ++sl)
            a += g_s2[sl * (B_ * 32) + k * B_ + b];
        s[k][b] = a;
    }
    __syncthreads();
    if (tid < 512) {
        int bb = tid >> 1, j = tid & 1;
        float sv[16], v[16];
#pragma unroll
        for (int e = 0; e < 16; ++e) sv[e] = s[j * 16 + e][bb];
        squash16(sv, v);
#pragma unroll
        for (int e = 0; e < 16; ++e) out[bb * 32 + j * 16 + e] = v[e];
    }
}

extern "C" void kernel_launch(void* const* d_in, const int* in_sizes, int n_in,
                              void* d_out, int out_size) {
    const float4* X = (const float4*)d_in[0];   // x: [256, 6912, 8] f32
    const float4* W = (const float4*)d_in[1];   // W: [2, 6912, 16, 8] f32
    float* out = (float*)d_out;                 // v: [256, 2, 16] f32

    zero_kernel<<<(SLOTS * B_ * 32 + 255) / 256, 256>>>();

    dim3 g1(NIN_ / NPB, B_ / 128);   // 288 x 2
    pass1_kernel<<<g1, P1_THR>>>(X, W);

    v1_kernel<<<1, 1024>>>();

    dim3 g2(NIN_ / NPB, B_ / 128);   // 288 x 2
    pass2_kernel<<<g2, P2_THR>>>(X, W);

    squash_out_kernel<<<1, 1024>>>(out);
}

// round 10
// speedup vs baseline: 1.3974x; 1.0026x over previous
#include <cuda_runtime.h>
#include <math.h>
#include <stdint.h>

#define B_    256
#define NIN_  6912
#define SLOTS 8

#define NPB   24            // n per block
#define NST   2             // n per stage
#define NSTG  (NPB / NST)   // 12 stages
#define NBUF  3

typedef unsigned long long ull;

#define FFMA2(d, a, b, c) \
    asm("fma.rn.f32x2 %0, %1, %2, %3;" : "=l"(d) : "l"(a), "l"(b), "l"(c))
#define FMUL2(d, a, b) \
    asm("mul.rn.f32x2 %0, %1, %2;" : "=l"(d) : "l"(a), "l"(b))
#define PACK2(d, lo, hi) \
    asm("mov.b64 %0, {%1, %2};" : "=l"(d) : "f"(lo), "f"(hi))
#define UNPACK2(lo, hi, v) \
    asm("mov.b64 {%0, %1}, %2;" : "=f"(lo), "=f"(hi) : "l"(v))

__device__ __forceinline__ uint32_t s2u(const void* p) {
    return (uint32_t)__cvta_generic_to_shared(p);
}
__device__ __forceinline__ void cp16(const void* sdst, const void* gsrc) {
    asm volatile("cp.async.cg.shared.global [%0], [%1], 16;"
                 :: "r"(s2u(sdst)), "l"(gsrc) : "memory");
}
#define CP_COMMIT() asm volatile("cp.async.commit_group;" ::: "memory")
template <int N>
__device__ __forceinline__ void cp_wait() {
    asm volatile("cp.async.wait_group %0;" :: "n"(N) : "memory");
}

// Scratch: s1/s2 transposed [slot][k][b] (k=j*16+e); v1 [b][k].
__device__ float g_s1[SLOTS * B_ * 32];
__device__ float g_s2[SLOTS * B_ * 32];
__device__ __align__(16) float g_v1[B_ * 32];

__global__ void zero_kernel() {
    int i = blockIdx.x * blockDim.x + threadIdx.x;
    if (i < SLOTS * B_ * 32) { g_s1[i] = 0.0f; g_s2[i] = 0.0f; }
}

__device__ __forceinline__ void squash16(const float* s, float* v) {
    float n2 = 0.0f;
#pragma unroll
    for (int e = 0; e < 16; ++e) n2 = fmaf(s[e], s[e], n2);
    float f = n2 / ((1.0f + n2) * sqrtf(n2 + 1e-9f));
#pragma unroll
    for (int e = 0; e < 16; ++e) v[e] = s[e] * f;
}

// W stage mapping (both passes): 128 float4 per stage, coalesced gmem reads.
// Wd[buf][nl][e][h][j]; strides (f4): j=1, h=2, e=4, nl=64.
#define STAGE_W(Wd, buf, n0, f)                                               \
    do {                                                                      \
        int h_ = (f) & 1, e_ = ((f) >> 1) & 15, jj_ = ((f) >> 5) & 1,         \
            nl_ = ((f) >> 6) & 1;                                             \
        cp16(&Wd[buf][nl_][e_][h_][jj_],                                      \
             Wg + ((size_t)(jj_ * NIN_ + (n0) + nl_) * 16 + e_) * 2 + h_);    \
    } while (0)

// ======================= Pass 1 =======================
// 128 threads = 4 warps. Lane: j = l&1, eh = (l>>1)&1, bq = l>>2.
// Thread: capsule j, e = 2*ei+eh (ei 0..7), 4 b's: lb_i = w*32 + i*8 + bq.
// Block covers 128 b; grid = (288, 2).
#define P1_THR 128

__global__ __launch_bounds__(P1_THR, 4) void pass1_kernel(const float4* __restrict__ X,
                                                          const float4* __restrict__ Wg) {
    __shared__ float4 Wd[NBUF][NST][16][2][2];
    __shared__ float4 xs[NBUF][128][NST * 2 + 1];   // row = 5 f4 = 80B

    const int tid  = threadIdx.x;
    const int w    = tid >> 5;
    const int lane = tid & 31;
    const int j    = lane & 1;
    const int eh   = (lane >> 1) & 1;
    const int bq   = lane >> 2;
    const int gbb  = blockIdx.y * 128;
    const int nbase = blockIdx.x * NPB;

    int lb[4];
#pragma unroll
    for (int i = 0; i < 4; ++i) lb[i] = w * 32 + i * 8 + bq;

    ull acc[4][8];                      // [b][ei], d-pair packed
    ull zero; PACK2(zero, 0.0f, 0.0f);
#pragma unroll
    for (int i = 0; i < 4; ++i)
#pragma unroll
        for (int ei = 0; ei < 8; ++ei) acc[i][ei] = zero;

    auto issue = [&](int s) {
        const int buf = s % NBUF;
        const int n0  = nbase + s * NST;
        STAGE_W(Wd, buf, n0, tid);
#pragma unroll
        for (int it = 0; it < 4; ++it) {   // x: 512 f4, 4 per thread
            int f = it * P1_THR + tid;
            int bl = f >> 2, q = f & 3;
            cp16(&xs[buf][bl][q],
                 X + ((size_t)(gbb + bl) * NIN_ + n0 + (q >> 1)) * 2 + (q & 1));
        }
        CP_COMMIT();
    };

    auto compute = [&](int s) {
        const int buf = s % NBUF;
#pragma unroll
        for (int nl = 0; nl < NST; ++nl) {
            ulonglong2 xv[4][2];
#pragma unroll
            for (int i = 0; i < 4; ++i) {
                xv[i][0] = *reinterpret_cast<const ulonglong2*>(&xs[buf][lb[i]][nl * 2]);
                xv[i][1] = *reinterpret_cast<const ulonglong2*>(&xs[buf][lb[i]][nl * 2 + 1]);
            }
#pragma unroll
            for (int ei = 0; ei < 8; ++ei) {
                const int e = 2 * ei + eh;
                const ulonglong2 wA = *reinterpret_cast<const ulonglong2*>(&Wd[buf][nl][e][0][j]);
                const ulonglong2 wB = *reinterpret_cast<const ulonglong2*>(&Wd[buf][nl][e][1][j]);
#pragma unroll
                for (int i = 0; i < 4; ++i) {
                    ull a = acc[i][ei];
                    FFMA2(a, wA.x, xv[i][0].x, a);
                    FFMA2(a, wA.y, xv[i][0].y, a);
                    FFMA2(a, wB.x, xv[i][1].x, a);
                    FFMA2(a, wB.y, xv[i][1].y, a);
                    acc[i][ei] = a;
                }
            }
        }
    };

    issue(0);
    issue(1);
#pragma unroll 3
    for (int s = 0; s < NSTG; ++s) {
        cp_wait<1>();
        __syncthreads();
        if (s + 2 < NSTG) issue(s + 2); else CP_COMMIT();
        compute(s);
    }

    float* dst = g_s1 + ((blockIdx.x + blockIdx.y) & (SLOTS - 1)) * (B_ * 32);
#pragma unroll
    for (int i = 0; i < 4; ++i)
#pragma unroll
        for (int ei = 0; ei < 8; ++ei) {
            float lo, hi;
            UNPACK2(lo, hi, acc[i][ei]);
            atomicAdd(dst + (j * 16 + 2 * ei + eh) * B_ + gbb + lb[i], lo + hi);
        }
}

// ======================= v1 = squash(0.5 * sum_slots s1) =======================
__global__ void v1_kernel() {
    __shared__ float s[32][B_];
    const int tid = threadIdx.x;
    const int b   = tid & 255;
    const int kg  = tid >> 8;
#pragma unroll
    for (int i = 0; i < 8; ++i) {
        int k = kg * 8 + i;
        float a = 0.0f;
#pragma unroll
        for (int sl = 0; sl < SLOTS; ++sl)
            a += g_s1[sl * (B_ * 32) + k * B_ + b];
        s[k][b] = a * 0.5f;
    }
    __syncthreads();
    if (tid < 512) {
        int bb = tid >> 1, j = tid & 1;
        float sv[16], v[16];
#pragma unroll
        for (int e = 0; e < 16; ++e) sv[e] = s[j * 16 + e][bb];
        squash16(sv, v);
#pragma unroll
        for (int e = 0; e < 16; ++e) g_v1[bb * 32 + j * 16 + e] = v[e];
    }
}

// ======================= Pass 2 =======================
// 256 threads = 8 warps. Lane: j = l&1, eh = (l>>1)&1, bq = l>>2.
// Thread: capsule j, e = {4q+eh, 4q+2+eh} (q 0..3), 2 b's: lbA = w*16+bq, lbB = +8.
// Block covers 128 b; grid = (288, 2). Logit reduced over eh via shfl xor 2.
#define P2_THR 256

__global__ __launch_bounds__(P2_THR, 2) void pass2_kernel(const float4* __restrict__ X,
                                                          const float4* __restrict__ Wg) {
    __shared__ float4 Wd[NBUF][NST][16][2][2];
    __shared__ float4 xs[NBUF][128][NST * 2 + 1];

    const int tid  = threadIdx.x;
    const int w    = tid >> 5;
    const int lane = tid & 31;
    const int j    = lane & 1;
    const int eh   = (lane >> 1) & 1;
    const int bq   = lane >> 2;
    const int lbA  = w * 16 + bq;
    const int lbB  = lbA + 8;
    const int gbb  = blockIdx.y * 128;
    const int bA   = gbb + lbA;
    const int bB   = gbb + lbB;
    const int nbase = blockIdx.x * NPB;

    // v1 for my e-subset, packed pairs matching u2 packing
    ull v1p[2][4];
#pragma unroll
    for (int q = 0; q < 4; ++q) {
        PACK2(v1p[0][q], g_v1[bA * 32 + j * 16 + 4 * q + eh],
                         g_v1[bA * 32 + j * 16 + 4 * q + 2 + eh]);
        PACK2(v1p[1][q], g_v1[bB * 32 + j * 16 + 4 * q + eh],
                         g_v1[bB * 32 + j * 16 + 4 * q + 2 + eh]);
    }

    ull accp[2][4];
    ull zero; PACK2(zero, 0.0f, 0.0f);
#pragma unroll
    for (int p = 0; p < 2; ++p)
#pragma unroll
        for (int q = 0; q < 4; ++q) accp[p][q] = zero;

    auto issue = [&](int s) {
        const int buf = s % NBUF;
        const int n0  = nbase + s * NST;
        if (tid < 128) STAGE_W(Wd, buf, n0, tid);
#pragma unroll
        for (int it = 0; it < 2; ++it) {   // x: 512 f4, 2 per thread
            int f = it * P2_THR + tid;
            int bl = f >> 2, q = f & 3;
            cp16(&xs[buf][bl][q],
                 X + ((size_t)(gbb + bl) * NIN_ + n0 + (q >> 1)) * 2 + (q & 1));
        }
        CP_COMMIT();
    };

    auto compute = [&](int s) {
        const int buf = s % NBUF;
#pragma unroll
        for (int nl = 0; nl < NST; ++nl) {
            const ulonglong2 xA0 = *reinterpret_cast<const ulonglong2*>(&xs[buf][lbA][nl * 2]);
            const ulonglong2 xA1 = *reinterpret_cast<const ulonglong2*>(&xs[buf][lbA][nl * 2 + 1]);
            const ulonglong2 xB0 = *reinterpret_cast<const ulonglong2*>(&xs[buf][lbB][nl * 2]);
            const ulonglong2 xB1 = *reinterpret_cast<const ulonglong2*>(&xs[buf][lbB][nl * 2 + 1]);

            ull u2A[4], u2B[4];
            ull t2A = zero, t2B = zero;
#pragma unroll
            for (int q = 0; q < 4; ++q) {
                const int e0 = 4 * q + eh, e1 = 4 * q + 2 + eh;
                const ulonglong2 w0A = *reinterpret_cast<const ulonglong2*>(&Wd[buf][nl][e0][0][j]);
                const ulonglong2 w0B = *reinterpret_cast<const ulonglong2*>(&Wd[buf][nl][e0][1][j]);
                const ulonglong2 w1A = *reinterpret_cast<const ulonglong2*>(&Wd[buf][nl][e1][0][j]);
                const ulonglong2 w1B = *reinterpret_cast<const ulonglong2*>(&Wd[buf][nl][e1][1][j]);

                ull tA0, tA1, tB0, tB1;
                FMUL2(tA0, w0A.x, xA0.x);
                FFMA2(tA0, w0A.y, xA0.y, tA0);
                FFMA2(tA0, w0B.x, xA1.x, tA0);
                FFMA2(tA0, w0B.y, xA1.y, tA0);
                FMUL2(tA1, w1A.x, xA0.x);
                FFMA2(tA1, w1A.y, xA0.y, tA1);
                FFMA2(tA1, w1B.x, xA1.x, tA1);
                FFMA2(tA1, w1B.y, xA1.y, tA1);
                FMUL2(tB0, w0A.x, xB0.x);
                FFMA2(tB0, w0A.y, xB0.y, tB0);
                FFMA2(tB0, w0B.x, xB1.x, tB0);
                FFMA2(tB0, w0B.y, xB1.y, tB0);
                FMUL2(tB1, w1A.x, xB0.x);
                FFMA2(tB1, w1A.y, xB0.y, tB1);
                FFMA2(tB1, w1B.x, xB1.x, tB1);
                FFMA2(tB1, w1B.y, xB1.y, tB1);

                float a0l, a0h, a1l, a1h, b0l, b0h, b1l, b1h;
                UNPACK2(a0l, a0h, tA0); UNPACK2(a1l, a1h, tA1);
                UNPACK2(b0l, b0h, tB0); UNPACK2(b1l, b1h, tB1);
                PACK2(u2A[q], a0l + a0h, a1l + a1h);
                PACK2(u2B[q], b0l + b0h, b1l + b1h);
                FFMA2(t2A, v1p[0][q], u2A[q], t2A);
                FFMA2(t2B, v1p[1][q], u2B[q], t2B);
            }

            float lo, hi, tA, tB;
            UNPACK2(lo, hi, t2A); tA = lo + hi;
            UNPACK2(lo, hi, t2B); tB = lo + hi;
            // reduce over eh lanes (xor 2) -> full 16-e logit for (b, j)
            tA += __shfl_xor_sync(0xffffffffu, tA, 2);
            tB += __shfl_xor_sync(0xffffffffu, tB, 2);
            // partner capsule's logit (xor 1)
            float toA = __shfl_xor_sync(0xffffffffu, tA, 1);
            float toB = __shfl_xor_sync(0xffffffffu, tB, 1);
            float cA = __fdividef(1.0f, 1.0f + __expf(toA - tA));
            float cB = __fdividef(1.0f, 1.0f + __expf(toB - tB));
            ull cdA, cdB;
            PACK2(cdA, cA, cA);
            PACK2(cdB, cB, cB);
#pragma unroll
            for (int q = 0; q < 4; ++q) {
                FFMA2(accp[0][q], cdA, u2A[q], accp[0][q]);
                FFMA2(accp[1][q], cdB, u2B[q], accp[1][q]);
            }
        }
    };

    issue(0);
    issue(1);
#pragma unroll 3
    for (int s = 0; s < NSTG; ++s) {
        cp_wait<1>();
        __syncthreads();
        if (s + 2 < NSTG) issue(s + 2); else CP_COMMIT();
        compute(s);
    }

    float* dst = g_s2 + ((blockIdx.x + blockIdx.y) & (SLOTS - 1)) * (B_ * 32);
#pragma unroll
    for (int q = 0; q < 4; ++q) {
        float lo, hi;
        UNPACK2(lo, hi, accp[0][q]);
        atomicAdd(dst + (j * 16 + 4 * q + eh) * B_ + bA,     lo);
        atomicAdd(dst + (j * 16 + 4 * q + 2 + eh) * B_ + bA, hi);
        UNPACK2(lo, hi, accp[1][q]);
        atomicAdd(dst + (j * 16 + 4 * q + eh) * B_ + bB,     lo);
        atomicAdd(dst + (j * 16 + 4 * q + 2 + eh) * B_ + bB, hi);
    }
}

// ======================= Output: v = squash(sum_slots s2) =======================
__global__ void squash_out_kernel(float* __restrict__ out) {
    __shared__ float s[32][B_];
    const int tid = threadIdx.x;
    const int b   = tid & 255;
    const int kg  = tid >> 8;
#pragma unroll
    for (int i = 0; i < 8; ++i) {
        int k = kg * 8 + i;
        float a = 0.0f;
#pragma unroll
        for (int sl = 0; sl < SLOTS; ++sl)
            a += g_s2[sl * (B_ * 32) + k * B_ + b];
        s[k][b] = a;
    }
    __syncthreads();
    if (tid < 512) {
        int bb = tid >> 1, j = tid & 1;
        float sv[16], v[16];
#pragma unroll
        for (int e = 0; e < 16; ++e) sv[e] = s[j * 16 + e][bb];
        squash16(sv, v);
#pragma unroll
        for (int e = 0; e < 16; ++e) out[bb * 32 + j * 16 + e] = v[e];
    }
}

extern "C" void kernel_launch(void* const* d_in, const int* in_sizes, int n_in,
                              void* d_out, int out_size) {
    const float4* X = (const float4*)d_in[0];   // x: [256, 6912, 8] f32
    const float4* W = (const float4*)d_in[1];   // W: [2, 6912, 16, 8] f32
    float* out = (float*)d_out;                 // v: [256, 2, 16] f32

    zero_kernel<<<(SLOTS * B_ * 32 + 255) / 256, 256>>>();

    dim3 g1(NIN_ / NPB, B_ / 128);   // 288 x 2
    pass1_kernel<<<g1, P1_THR>>>(X, W);

    v1_kernel<<<1, 1024>>>();

    dim3 g2(NIN_ / NPB, B_ / 128);   // 288 x 2
    pass2_kernel<<<g2, P2_THR>>>(X, W);

    squash_out_kernel<<<1, 1024>>>(out);
}